// round 9
// baseline (speedup 1.0000x reference)
#include <cuda_runtime.h>
#include <math_constants.h>

// Problem constants (fixed shapes from reference setup_inputs)
#define B 128
#define C 128
#define HW 4096          // 64*64
#define NPLANES (B*C)    // 16384
#define LIFETIME_K 6

// Scratch (no cudaMalloc allowed)
__device__ float    g_pooledT[NPLANES];  // transposed: [C, B] for coalesced topk loads
__device__ int      g_pidx[NPLANES];     // plane-indexed: [B, C]
__device__ unsigned g_arrive;            // zero-initialized; self-resets each launch

// ---------------------------------------------------------------------------
// Single fused kernel.
// Phase 1 (all 16384 blocks, one plane each):
//   - issue the 4 float4 input loads FIRST (the blocking dependency),
//   - then 4 independent float4 zero-stores to the output plane (overlapped
//     store stream; streaming hints keep zero-reuse lines out of L2 residency),
//   - max + first-argmax reduction -> pooledT (transposed) + pidx.
// Phase 2 (last arriving block only, via threadfence-reduction pattern):
//   - 8 warps x 16 features: register-only top-6 over batch (value desc,
//     batch-index asc on ties = jax.lax.top_k stability), then point-scatter
//     out[plane*HW + pidx[plane]] = life (0 for non-selected planes, which is
//     value-identical to the zero background). pooledT/pidx are L2-resident.
// ---------------------------------------------------------------------------
__global__ __launch_bounds__(256) void fused_kernel(const float* __restrict__ in,
                                                    float* __restrict__ out,
                                                    float* __restrict__ pooledT,
                                                    int* __restrict__ pidx) {
    const int plane = blockIdx.x;
    const int t = threadIdx.x;

    // ---- loads first: 4 independent LDG.128 in flight immediately ----
    const float4* p = reinterpret_cast<const float4*>(in + (size_t)plane * HW);
    float4 va[4];
    va[0] = __ldcs(p + t);
    va[1] = __ldcs(p + t + 256);
    va[2] = __ldcs(p + t + 512);
    va[3] = __ldcs(p + t + 768);

    // ---- independent zero stores for this plane's output (16 KB) ----
    {
        const float4 z = make_float4(0.f, 0.f, 0.f, 0.f);
        float4* o = reinterpret_cast<float4*>(out) + (size_t)plane * (HW / 4) + t;
        __stcs(o,       z);
        __stcs(o + 256, z);
        __stcs(o + 512, z);
        __stcs(o + 768, z);
    }

    // ---- max + first-argmax over the 16 values this thread owns ----
    float best = -CUDART_INF_F;
    int   bi   = 0x7fffffff;
    #pragma unroll
    for (int k = 0; k < 4; k++) {
        const int base = (t + k * 256) * 4;
        const float4 v = va[k];
        // within-thread indices strictly increasing -> strict > keeps first max
        if (v.x > best) { best = v.x; bi = base + 0; }
        if (v.y > best) { best = v.y; bi = base + 1; }
        if (v.z > best) { best = v.z; bi = base + 2; }
        if (v.w > best) { best = v.w; bi = base + 3; }
    }

    // warp reduce (value desc, index asc on ties -> first-max semantics)
    #pragma unroll
    for (int o = 16; o; o >>= 1) {
        const float ov = __shfl_down_sync(0xffffffffu, best, o);
        const int   oi = __shfl_down_sync(0xffffffffu, bi,   o);
        if (ov > best || (ov == best && oi < bi)) { best = ov; bi = oi; }
    }

    __shared__ float sv[8];
    __shared__ int   si[8];
    const int warp = t >> 5;
    const int lane = t & 31;
    if (lane == 0) { sv[warp] = best; si[warp] = bi; }
    __syncthreads();

    if (warp == 0) {
        best = (lane < 8) ? sv[lane] : -CUDART_INF_F;
        bi   = (lane < 8) ? si[lane] : 0x7fffffff;
        #pragma unroll
        for (int o = 4; o; o >>= 1) {
            const float ov = __shfl_down_sync(0xffffffffu, best, o);
            const int   oi = __shfl_down_sync(0xffffffffu, bi,   o);
            if (ov > best || (ov == best && oi < bi)) { best = ov; bi = oi; }
        }
        if (lane == 0) {
            const int c = plane & (C - 1);
            const int b = plane >> 7;        // plane / C
            pooledT[c * B + b] = best;       // transposed store
            pidx[plane] = bi;
        }
    }

    // ---- arrival: threadfence-reduction last-block election ----
    __syncthreads();                 // all stores of this block are program-complete
    __shared__ bool isLast;
    if (t == 0) {
        __threadfence();             // publish this block's stores device-wide
        const unsigned old = atomicAdd(&g_arrive, 1u);
        isLast = (old == NPLANES - 1);
        if (isLast) g_arrive = 0;    // reset for next graph replay (all arrived)
    }
    __syncthreads();
    if (!isLast) return;

    if (t == 0) __threadfence();     // acquire side of the chain
    __syncthreads();

    // ---- epilogue: warp-per-feature top-6 + scatter (8 warps x 16 features) ----
    #pragma unroll 2
    for (int i = 0; i < 16; i++) {
        const int c = warp * 16 + i;

        // lane owns batches b = lane, lane+32, lane+64, lane+96
        float v[4], cur[4];
        #pragma unroll
        for (int k = 0; k < 4; k++) {
            v[k] = pooledT[c * B + lane + k * 32];
            cur[k] = v[k];
        }
        unsigned selmask = 0;

        #pragma unroll
        for (int r = 0; r < LIFETIME_K; r++) {
            // local argmax: k ascending means b ascending, strict > keeps smallest b
            float lv = cur[0]; int lk = 0;
            #pragma unroll
            for (int k = 1; k < 4; k++)
                if (cur[k] > lv) { lv = cur[k]; lk = k; }
            float bv = lv;
            int   bb = lane + lk * 32;       // global batch index

            // butterfly reduce: max value, tie -> smaller batch index
            #pragma unroll
            for (int o = 16; o; o >>= 1) {
                const float ov = __shfl_xor_sync(0xffffffffu, bv, o);
                const int   ob = __shfl_xor_sync(0xffffffffu, bb, o);
                if (ov > bv || (ov == bv && ob < bb)) { bv = ov; bb = ob; }
            }
            // winner lane retires its value
            if ((bb & 31) == lane) {
                const int k = bb >> 5;
                cur[k] = -CUDART_INF_F;
                selmask |= 1u << k;
            }
        }

        // scatter: each lane writes its 4 planes' single elements
        #pragma unroll
        for (int k = 0; k < 4; k++) {
            const int b = lane + k * 32;
            const int pl = b * C + c;
            const float life = ((selmask >> k) & 1u) ? v[k] : 0.0f;
            out[(size_t)pl * HW + pidx[pl]] = life;
        }
    }
}

// ---------------------------------------------------------------------------
extern "C" void kernel_launch(void* const* d_in, const int* in_sizes, int n_in,
                              void* d_out, int out_size) {
    const float* act = (const float*)d_in[0];
    float* out = (float*)d_out;

    float* pooledT; cudaGetSymbolAddress((void**)&pooledT, g_pooledT);
    int*   pidx;    cudaGetSymbolAddress((void**)&pidx,    g_pidx);

    fused_kernel<<<NPLANES, 256>>>(act, out, pooledT, pidx);
}

// round 11
// speedup vs baseline: 1.3645x; 1.3645x over previous
#include <cuda_runtime.h>
#include <math_constants.h>

// Problem constants (fixed shapes from reference setup_inputs)
#define B 128
#define C 128
#define HW 4096          // 64*64
#define NPLANES (B*C)    // 16384
#define LIFETIME_K 6

// Scratch (no cudaMalloc allowed)
__device__ float g_pooledT[NPLANES];   // transposed: [C, B] for coalesced topk loads
__device__ int   g_pidx[NPLANES];      // plane-indexed: [B, C]

// ---------------------------------------------------------------------------
// Kernel 1 (fused): per-plane zero-fill of the output plane PLUS
// max + first-argmax over the 4096-float input plane.  (Exact R8 version:
// proven 79.6us @ ~80% DRAM, 24 regs. Stores issued first; loads interleave.)
// ---------------------------------------------------------------------------
__global__ __launch_bounds__(256) void pool_zero_kernel(const float* __restrict__ in,
                                                        float4* __restrict__ out4,
                                                        float* __restrict__ pooledT,
                                                        int* __restrict__ pidx) {
    const int plane = blockIdx.x;
    const int t = threadIdx.x;

    // ---- independent zero stores for this plane's output (16 KB) ----
    {
        const float4 z = make_float4(0.f, 0.f, 0.f, 0.f);
        float4* o = out4 + (size_t)plane * (HW / 4) + t;
        #pragma unroll
        for (int k = 0; k < 4; k++)
            __stcs(o + k * 256, z);
    }

    // ---- input reduction: max + first-argmax ----
    const float4* p = reinterpret_cast<const float4*>(in + (size_t)plane * HW);

    float best = -CUDART_INF_F;
    int   bi   = 0x7fffffff;

    #pragma unroll
    for (int k = 0; k < 4; k++) {
        const int v4 = t + k * 256;          // float4 index, coalesced across warp
        const float4 v = __ldcs(p + v4);
        const int base = v4 * 4;
        // within-thread indices are strictly increasing -> strict > keeps first max
        if (v.x > best) { best = v.x; bi = base + 0; }
        if (v.y > best) { best = v.y; bi = base + 1; }
        if (v.z > best) { best = v.z; bi = base + 2; }
        if (v.w > best) { best = v.w; bi = base + 3; }
    }

    // warp reduce (value desc, index asc on ties -> first-max semantics)
    #pragma unroll
    for (int o = 16; o; o >>= 1) {
        const float ov = __shfl_down_sync(0xffffffffu, best, o);
        const int   oi = __shfl_down_sync(0xffffffffu, bi,   o);
        if (ov > best || (ov == best && oi < bi)) { best = ov; bi = oi; }
    }

    __shared__ float sv[8];
    __shared__ int   si[8];
    const int warp = t >> 5;
    const int lane = t & 31;
    if (lane == 0) { sv[warp] = best; si[warp] = bi; }
    __syncthreads();

    if (warp == 0) {
        best = (lane < 8) ? sv[lane] : -CUDART_INF_F;
        bi   = (lane < 8) ? si[lane] : 0x7fffffff;
        #pragma unroll
        for (int o = 4; o; o >>= 1) {
            const float ov = __shfl_down_sync(0xffffffffu, best, o);
            const int   oi = __shfl_down_sync(0xffffffffu, bi,   o);
            if (ov > best || (ov == best && oi < bi)) { best = ov; bi = oi; }
        }
        if (lane == 0) {
            const int c = plane & (C - 1);
            const int b = plane >> 7;        // plane / C
            pooledT[c * B + b] = best;       // transposed store
            pidx[plane] = bi;
        }
    }
}

// ---------------------------------------------------------------------------
// Kernel 2: warp-per-feature top-6 over batch + fused point scatter.
// Launched with PDL (programmatic stream serialization): the grid is set up
// on SMs while pool_zero is still running; cudaGridDependencySynchronize()
// blocks until the primary grid fully completes (implicit trigger at primary
// block exit => full memory visibility of pooledT/pidx/zeros).
// 32 blocks x 128 threads; warp w of block g handles feature c = g*4+w.
// Tie-breaks match jax.lax.top_k stability (value desc, batch asc).
// ---------------------------------------------------------------------------
__global__ __launch_bounds__(128) void topk_scatter_kernel(const float* __restrict__ pooledT,
                                                           const int* __restrict__ pidx,
                                                           float* __restrict__ out) {
    cudaGridDependencySynchronize();

    const int warp = threadIdx.x >> 5;
    const int lane = threadIdx.x & 31;
    const int c = blockIdx.x * 4 + warp;

    // lane owns batches b = lane, lane+32, lane+64, lane+96 (in-thread b ascending)
    float v[4];
    #pragma unroll
    for (int k = 0; k < 4; k++)
        v[k] = pooledT[c * B + lane + k * 32];

    float cur[4] = {v[0], v[1], v[2], v[3]};
    unsigned selmask = 0;

    #pragma unroll
    for (int r = 0; r < LIFETIME_K; r++) {
        // local argmax: k ascending means b ascending, strict > keeps smallest b
        float lv = cur[0]; int lk = 0;
        #pragma unroll
        for (int k = 1; k < 4; k++)
            if (cur[k] > lv) { lv = cur[k]; lk = k; }
        float bv = lv;
        int   bb = lane + lk * 32;           // global batch index

        // butterfly reduce: max value, tie -> smaller batch index
        #pragma unroll
        for (int o = 16; o; o >>= 1) {
            const float ov = __shfl_xor_sync(0xffffffffu, bv, o);
            const int   ob = __shfl_xor_sync(0xffffffffu, bb, o);
            if (ov > bv || (ov == bv && ob < bb)) { bv = ov; bb = ob; }
        }
        // winner lane retires its value
        if ((bb & 31) == lane) {
            const int k = bb >> 5;
            cur[k] = -CUDART_INF_F;
            selmask |= 1u << k;
        }
    }

    // scatter: each lane writes its 4 planes' single elements
    #pragma unroll
    for (int k = 0; k < 4; k++) {
        const int b = lane + k * 32;
        const int plane = b * C + c;
        const float life = ((selmask >> k) & 1u) ? v[k] : 0.0f;
        out[(size_t)plane * HW + pidx[plane]] = life;
    }
}

// ---------------------------------------------------------------------------
extern "C" void kernel_launch(void* const* d_in, const int* in_sizes, int n_in,
                              void* d_out, int out_size) {
    const float* act = (const float*)d_in[0];
    float* out = (float*)d_out;

    float* pooledT; cudaGetSymbolAddress((void**)&pooledT, g_pooledT);
    int*   pidx;    cudaGetSymbolAddress((void**)&pidx,    g_pidx);

    pool_zero_kernel<<<NPLANES, 256>>>(act, (float4*)out, pooledT, pidx);

    // PDL launch of the dependent epilogue kernel
    cudaLaunchConfig_t cfg = {};
    cfg.gridDim = dim3(C / 4);
    cfg.blockDim = dim3(128);
    cfg.dynamicSmemBytes = 0;
    cfg.stream = 0;  // same (captured) default stream
    cudaLaunchAttribute attrs[1];
    attrs[0].id = cudaLaunchAttributeProgrammaticStreamSerialization;
    attrs[0].val.programmaticStreamSerializationAllowed = 1;
    cfg.attrs = attrs;
    cfg.numAttrs = 1;
    cudaLaunchKernelEx(&cfg, topk_scatter_kernel,
                       (const float*)pooledT, (const int*)pidx, out);
}

// round 14
// speedup vs baseline: 1.3727x; 1.0060x over previous
#include <cuda_runtime.h>
#include <math_constants.h>

// Problem constants (fixed shapes from reference setup_inputs)
#define B 128
#define C 128
#define HW 4096          // 64*64
#define NPLANES (B*C)    // 16384
#define LIFETIME_K 6

// Scratch (no cudaMalloc allowed) — both transposed [C, B] for coalesced tail loads
__device__ float g_pooledT[NPLANES];
__device__ int   g_pidxT[NPLANES];

// ---------------------------------------------------------------------------
// Kernel 1 (fused): per-plane zero-fill of the output plane PLUS
// max + first-argmax over the 4096-float input plane.  (Proven R8 body:
// 79.6us @ ~80% DRAM, 24 regs. Stores issued first; loads interleave.)
// pooled/pidx written TRANSPOSED so the tail kernel loads coalesced.
// ---------------------------------------------------------------------------
__global__ __launch_bounds__(256) void pool_zero_kernel(const float* __restrict__ in,
                                                        float4* __restrict__ out4,
                                                        float* __restrict__ pooledT,
                                                        int* __restrict__ pidxT) {
    const int plane = blockIdx.x;
    const int t = threadIdx.x;

    // ---- independent zero stores for this plane's output (16 KB) ----
    {
        const float4 z = make_float4(0.f, 0.f, 0.f, 0.f);
        float4* o = out4 + (size_t)plane * (HW / 4) + t;
        #pragma unroll
        for (int k = 0; k < 4; k++)
            __stcs(o + k * 256, z);
    }

    // ---- input reduction: max + first-argmax ----
    const float4* p = reinterpret_cast<const float4*>(in + (size_t)plane * HW);

    float best = -CUDART_INF_F;
    int   bi   = 0x7fffffff;

    #pragma unroll
    for (int k = 0; k < 4; k++) {
        const int v4 = t + k * 256;          // float4 index, coalesced across warp
        const float4 v = __ldcs(p + v4);
        const int base = v4 * 4;
        // within-thread indices are strictly increasing -> strict > keeps first max
        if (v.x > best) { best = v.x; bi = base + 0; }
        if (v.y > best) { best = v.y; bi = base + 1; }
        if (v.z > best) { best = v.z; bi = base + 2; }
        if (v.w > best) { best = v.w; bi = base + 3; }
    }

    // warp reduce (value desc, index asc on ties -> first-max semantics)
    #pragma unroll
    for (int o = 16; o; o >>= 1) {
        const float ov = __shfl_down_sync(0xffffffffu, best, o);
        const int   oi = __shfl_down_sync(0xffffffffu, bi,   o);
        if (ov > best || (ov == best && oi < bi)) { best = ov; bi = oi; }
    }

    __shared__ float sv[8];
    __shared__ int   si[8];
    const int warp = t >> 5;
    const int lane = t & 31;
    if (lane == 0) { sv[warp] = best; si[warp] = bi; }
    __syncthreads();

    if (warp == 0) {
        best = (lane < 8) ? sv[lane] : -CUDART_INF_F;
        bi   = (lane < 8) ? si[lane] : 0x7fffffff;
        #pragma unroll
        for (int o = 4; o; o >>= 1) {
            const float ov = __shfl_down_sync(0xffffffffu, best, o);
            const int   oi = __shfl_down_sync(0xffffffffu, bi,   o);
            if (ov > best || (ov == best && oi < bi)) { best = ov; bi = oi; }
        }
        if (lane == 0) {
            const int c = plane & (C - 1);
            const int b = plane >> 7;        // plane / C
            pooledT[c * B + b] = best;       // transposed stores
            pidxT[c * B + b] = bi;
        }
    }
}

// ---------------------------------------------------------------------------
// Kernel 2 (tail): one warp per feature, 128 blocks x 32 threads.
// All 8 loads (4 pooled values + 4 argmax indices, both coalesced from the
// transposed arrays) are issued up front — one L2 round trip at MLP=8 —
// before the serial butterfly chains. Top-6 over batch (value desc, batch
// asc on ties = jax.lax.top_k stability), then point-scatter.
// Launched with PDL so grid setup overlaps the primary's tail.
// ---------------------------------------------------------------------------
__global__ __launch_bounds__(32) void topk_scatter_kernel(const float* __restrict__ pooledT,
                                                          const int* __restrict__ pidxT,
                                                          float* __restrict__ out) {
    cudaGridDependencySynchronize();

    const int lane = threadIdx.x;
    const int c = blockIdx.x;

    // lane owns batches b = lane, lane+32, lane+64, lane+96 (in-thread b ascending)
    float v[4];
    int   ip[4];
    #pragma unroll
    for (int k = 0; k < 4; k++) {
        v[k]  = pooledT[c * B + lane + k * 32];
        ip[k] = pidxT [c * B + lane + k * 32];
    }

    float cur[4] = {v[0], v[1], v[2], v[3]};
    unsigned selmask = 0;

    #pragma unroll
    for (int r = 0; r < LIFETIME_K; r++) {
        // local argmax: k ascending means b ascending, strict > keeps smallest b
        float lv = cur[0]; int lk = 0;
        #pragma unroll
        for (int k = 1; k < 4; k++)
            if (cur[k] > lv) { lv = cur[k]; lk = k; }
        float bv = lv;
        int   bb = lane + lk * 32;           // global batch index

        // butterfly reduce: max value, tie -> smaller batch index
        #pragma unroll
        for (int o = 16; o; o >>= 1) {
            const float ov = __shfl_xor_sync(0xffffffffu, bv, o);
            const int   ob = __shfl_xor_sync(0xffffffffu, bb, o);
            if (ov > bv || (ov == bv && ob < bb)) { bv = ov; bb = ob; }
        }
        // winner lane retires its value
        if ((bb & 31) == lane) {
            const int k = bb >> 5;
            cur[k] = -CUDART_INF_F;
            selmask |= 1u << k;
        }
    }

    // scatter: each lane writes its 4 planes' single elements
    #pragma unroll
    for (int k = 0; k < 4; k++) {
        const int b = lane + k * 32;
        const int plane = b * C + c;
        const float life = ((selmask >> k) & 1u) ? v[k] : 0.0f;
        out[(size_t)plane * HW + ip[k]] = life;
    }
}

// ---------------------------------------------------------------------------
extern "C" void kernel_launch(void* const* d_in, const int* in_sizes, int n_in,
                              void* d_out, int out_size) {
    const float* act = (const float*)d_in[0];
    float* out = (float*)d_out;

    float* pooledT; cudaGetSymbolAddress((void**)&pooledT, g_pooledT);
    int*   pidxT;   cudaGetSymbolAddress((void**)&pidxT,   g_pidxT);

    pool_zero_kernel<<<NPLANES, 256>>>(act, (float4*)out, pooledT, pidxT);

    // PDL launch of the dependent epilogue kernel
    cudaLaunchConfig_t cfg = {};
    cfg.gridDim = dim3(C);
    cfg.blockDim = dim3(32);
    cfg.dynamicSmemBytes = 0;
    cfg.stream = 0;  // same (captured) default stream
    cudaLaunchAttribute attrs[1];
    attrs[0].id = cudaLaunchAttributeProgrammaticStreamSerialization;
    attrs[0].val.programmaticStreamSerializationAllowed = 1;
    cfg.attrs = attrs;
    cfg.numAttrs = 1;
    cudaLaunchKernelEx(&cfg, topk_scatter_kernel,
                       (const float*)pooledT, (const int*)pidxT, out);
}